// round 2
// baseline (speedup 1.0000x reference)
#include <cuda_runtime.h>
#include <cuda_fp16.h>
#include <cstdint>

// ---------------------------------------------------------------------------
// Problem dims (fixed by the reference setup_inputs)
// ---------------------------------------------------------------------------
constexpr int TOK = 4 * 2048;   // 8192 tokens (batch*seq)
constexpr int DIM = 2048;
constexpr int HID = 8192;
constexpr int QBLK = 64;

// ---------------------------------------------------------------------------
// Device scratch (static globals -- no runtime allocation allowed)
// ---------------------------------------------------------------------------
static __device__ __half g_xh [TOK * DIM];                 //  32 MB
static __device__ __half g_wfc[HID * DIM];                 //  32 MB
static __device__ __half g_wpj[DIM * HID];                 //  32 MB
static __device__ __half g_h2 [(size_t)TOK * HID];         // 128 MB

// ---------------------------------------------------------------------------
// Kernel 1: blockwise int5 MSE quant-dequant  (warp per 64-elem block)
// Replicates: base = max(amax,1e-8)/15; scan s in np.linspace(0.4,1.0,16);
// deq = clip(rint(w/scale),-15,15)*scale; keep scale of min MSE (strict <).
// ---------------------------------------------------------------------------
__global__ void quant_kernel(const float* __restrict__ w, int which, int nblk) {
    __half* wq = which ? g_wpj : g_wfc;
    int warp = (blockIdx.x * blockDim.x + threadIdx.x) >> 5;
    int lane = threadIdx.x & 31;
    if (warp >= nblk) return;

    const float* p = w + (size_t)warp * QBLK;
    float v0 = p[lane];
    float v1 = p[lane + 32];

    float a = fmaxf(fabsf(v0), fabsf(v1));
    #pragma unroll
    for (int o = 16; o; o >>= 1) a = fmaxf(a, __shfl_xor_sync(0xffffffffu, a, o));

    float base = __fdiv_rn(fmaxf(a, 1e-8f), 15.0f);
    float best_err = INFINITY;
    float best_scale = base;

    #pragma unroll 1
    for (int i = 0; i < 16; i++) {
        // np.linspace(0.4, 1.0, 16): double step, endpoint exact
        double sd = 0.4 + (double)i * (0.6 / 15.0);
        float s = (i == 15) ? 1.0f : (float)sd;
        float scale = base * s;
        float q0 = fminf(fmaxf(rintf(__fdiv_rn(v0, scale)), -15.f), 15.f);
        float q1 = fminf(fmaxf(rintf(__fdiv_rn(v1, scale)), -15.f), 15.f);
        float d0 = q0 * scale - v0;
        float d1 = q1 * scale - v1;
        float e = d0 * d0 + d1 * d1;
        #pragma unroll
        for (int o = 16; o; o >>= 1) e += __shfl_xor_sync(0xffffffffu, e, o);
        if (e < best_err) { best_err = e; best_scale = scale; }
    }

    float q0 = fminf(fmaxf(rintf(__fdiv_rn(v0, best_scale)), -15.f), 15.f);
    float q1 = fminf(fmaxf(rintf(__fdiv_rn(v1, best_scale)), -15.f), 15.f);
    wq[(size_t)warp * QBLK + lane]      = __float2half(q0 * best_scale);
    wq[(size_t)warp * QBLK + lane + 32] = __float2half(q1 * best_scale);
}

// ---------------------------------------------------------------------------
// Kernel 2: x fp32 -> fp16
// ---------------------------------------------------------------------------
__global__ void f2h_kernel(const float4* __restrict__ in, int n4) {
    int i = blockIdx.x * blockDim.x + threadIdx.x;
    if (i < n4) {
        float4 v = in[i];
        __half2* out = reinterpret_cast<__half2*>(g_xh);
        out[2 * i]     = __floats2half2_rn(v.x, v.y);
        out[2 * i + 1] = __floats2half2_rn(v.z, v.w);
    }
}

// ---------------------------------------------------------------------------
// GEMM core: C[M,N] = A[M,K] (row-major) @ B[N,K]^T (row-major, K-contig)
// 128x128x32 CTA tile, 8 warps (2x4), warp tile 64x32, m16n8k16 HMMA,
// cp.async 2-stage double buffer, padded smem (stride 40 halves => ldmatrix
// conflict-free since 80B * row hits distinct 16B lines mod 128B).
// Epilogue: RELU_SQ -> fp16 (relu(acc))^2 into Ch, else fp32 into Cf.
// All dims divisible by tiles -- no bounds checks.
// ---------------------------------------------------------------------------
__device__ __forceinline__ unsigned smem_u32(const void* p) {
    return (unsigned)__cvta_generic_to_shared(p);
}

template <bool RELU_SQ>
__device__ __forceinline__ void gemm_body(const __half* __restrict__ A,
                                          const __half* __restrict__ B,
                                          __half* __restrict__ Ch,
                                          float* __restrict__ Cf,
                                          int M, int N, int K) {
    constexpr int BM = 128, BN = 128, BK = 32, LDS = BK + 8;  // 40 halves

    __shared__ __align__(16) __half As[2][BM * LDS];
    __shared__ __align__(16) __half Bs[2][BN * LDS];

    const int tid  = threadIdx.x;
    const int lane = tid & 31;
    const int warp = tid >> 5;
    const int wm   = warp >> 2;   // 0..1
    const int wn   = warp & 3;    // 0..3
    const int bm   = blockIdx.y * BM;
    const int bn   = blockIdx.x * BN;

    auto stage_load = [&](int kt, int buf) {
        const int k0 = kt * BK;
        #pragma unroll
        for (int h = 0; h < 2; h++) {
            int c   = tid + h * 256;      // 512 16B-chunks per operand tile
            int r   = c >> 2;
            int col = (c & 3) * 8;
            const __half* gA = A + (size_t)(bm + r) * K + k0 + col;
            unsigned sa = smem_u32(&As[buf][r * LDS + col]);
            asm volatile("cp.async.cg.shared.global [%0],[%1],16;\n"
                         :: "r"(sa), "l"(gA) : "memory");
            const __half* gB = B + (size_t)(bn + r) * K + k0 + col;
            unsigned sb = smem_u32(&Bs[buf][r * LDS + col]);
            asm volatile("cp.async.cg.shared.global [%0],[%1],16;\n"
                         :: "r"(sb), "l"(gB) : "memory");
        }
        asm volatile("cp.async.commit_group;\n" ::: "memory");
    };

    float acc[4][4][4];
    #pragma unroll
    for (int i = 0; i < 4; i++)
        #pragma unroll
        for (int j = 0; j < 4; j++)
            #pragma unroll
            for (int k = 0; k < 4; k++) acc[i][j][k] = 0.f;

    const int nk = K / BK;
    stage_load(0, 0);

    for (int kt = 0; kt < nk; kt++) {
        const int cur = kt & 1;
        asm volatile("cp.async.wait_group 0;\n" ::: "memory");
        __syncthreads();
        if (kt + 1 < nk) stage_load(kt + 1, cur ^ 1);

        #pragma unroll
        for (int ks = 0; ks < 2; ks++) {
            uint32_t af[4][4];
            #pragma unroll
            for (int mi = 0; mi < 4; mi++) {
                int r = wm * 64 + mi * 16 + (lane & 15);
                int c = ks * 16 + (lane >> 4) * 8;
                unsigned addr = smem_u32(&As[cur][r * LDS + c]);
                asm volatile(
                    "ldmatrix.sync.aligned.m8n8.x4.shared.b16 {%0,%1,%2,%3},[%4];"
                    : "=r"(af[mi][0]), "=r"(af[mi][1]),
                      "=r"(af[mi][2]), "=r"(af[mi][3])
                    : "r"(addr));
            }
            uint32_t bf[4][2];
            #pragma unroll
            for (int nb = 0; nb < 2; nb++) {
                int t    = lane >> 3;  // 0..3: tiles (n-half, k-half)
                int nrow = wn * 32 + nb * 16 + (t >> 1) * 8 + (lane & 7);
                int c    = ks * 16 + (t & 1) * 8;
                unsigned addr = smem_u32(&Bs[cur][nrow * LDS + c]);
                uint32_t r0, r1, r2, r3;
                asm volatile(
                    "ldmatrix.sync.aligned.m8n8.x4.shared.b16 {%0,%1,%2,%3},[%4];"
                    : "=r"(r0), "=r"(r1), "=r"(r2), "=r"(r3) : "r"(addr));
                bf[nb * 2][0] = r0; bf[nb * 2][1] = r1;
                bf[nb * 2 + 1][0] = r2; bf[nb * 2 + 1][1] = r3;
            }
            #pragma unroll
            for (int mi = 0; mi < 4; mi++)
                #pragma unroll
                for (int ni = 0; ni < 4; ni++)
                    asm volatile(
                        "mma.sync.aligned.m16n8k16.row.col.f32.f16.f16.f32 "
                        "{%0,%1,%2,%3},{%4,%5,%6,%7},{%8,%9},{%0,%1,%2,%3};"
                        : "+f"(acc[mi][ni][0]), "+f"(acc[mi][ni][1]),
                          "+f"(acc[mi][ni][2]), "+f"(acc[mi][ni][3])
                        : "r"(af[mi][0]), "r"(af[mi][1]),
                          "r"(af[mi][2]), "r"(af[mi][3]),
                          "r"(bf[ni][0]), "r"(bf[ni][1]));
        }
        __syncthreads();
    }

    // Epilogue: c-frag (m16n8): c0,c1 at (lane/4, (lane%4)*2), c2,c3 at +8 rows
    const int row0 = bm + wm * 64 + (lane >> 2);
    const int col0 = bn + wn * 32 + (lane & 3) * 2;
    #pragma unroll
    for (int mi = 0; mi < 4; mi++)
        #pragma unroll
        for (int ni = 0; ni < 4; ni++) {
            int r = row0 + mi * 16;
            int c = col0 + ni * 8;
            if (RELU_SQ) {
                float x0 = fmaxf(acc[mi][ni][0], 0.f); x0 *= x0;
                float x1 = fmaxf(acc[mi][ni][1], 0.f); x1 *= x1;
                float y0 = fmaxf(acc[mi][ni][2], 0.f); y0 *= y0;
                float y1 = fmaxf(acc[mi][ni][3], 0.f); y1 *= y1;
                *reinterpret_cast<__half2*>(&Ch[(size_t)r * N + c]) =
                    __floats2half2_rn(x0, x1);
                *reinterpret_cast<__half2*>(&Ch[(size_t)(r + 8) * N + c]) =
                    __floats2half2_rn(y0, y1);
            } else {
                *reinterpret_cast<float2*>(&Cf[(size_t)r * N + c]) =
                    make_float2(acc[mi][ni][0], acc[mi][ni][1]);
                *reinterpret_cast<float2*>(&Cf[(size_t)(r + 8) * N + c]) =
                    make_float2(acc[mi][ni][2], acc[mi][ni][3]);
            }
        }
}

__global__ __launch_bounds__(256, 2) void gemm1_kernel() {
    // h2 = (relu(x @ wfc^T))^2, fp16
    gemm_body<true>(g_xh, g_wfc, g_h2, nullptr, TOK, HID, DIM);
}

__global__ __launch_bounds__(256, 2) void gemm2_kernel(float* __restrict__ out) {
    // out = h2 @ wproj^T, fp32
    gemm_body<false>(g_h2, g_wpj, nullptr, out, TOK, DIM, HID);
}

// ---------------------------------------------------------------------------
// Launch
// ---------------------------------------------------------------------------
extern "C" void kernel_launch(void* const* d_in, const int* in_sizes, int n_in,
                              void* d_out, int out_size) {
    const float* x   = (const float*)d_in[0];
    const float* wfc = (const float*)d_in[1];
    const float* wpj = (const float*)d_in[2];
    float* out = (float*)d_out;

    // x fp32 -> fp16
    int n4 = TOK * DIM / 4;
    f2h_kernel<<<(n4 + 255) / 256, 256>>>((const float4*)x, n4);

    // quantize both weights (warp per 64-block)
    int nblk = HID * DIM / QBLK;                        // 262144 for each
    int qblocks = (nblk * 32 + 255) / 256;              // 32768 CTAs
    quant_kernel<<<qblocks, 256>>>(wfc, 0, nblk);
    quant_kernel<<<qblocks, 256>>>(wpj, 1, nblk);

    // GEMM1: [8192,8192] = x @ wfc^T, fused relu^2 -> fp16 scratch
    gemm1_kernel<<<dim3(HID / 128, TOK / 128), 256>>>();

    // GEMM2: [8192,2048] = h2 @ wproj^T -> fp32 out
    gemm2_kernel<<<dim3(DIM / 128, TOK / 128), 256>>>(out);

    (void)in_sizes; (void)n_in; (void)out_size;
}

// round 5
// speedup vs baseline: 1.2435x; 1.2435x over previous
#include <cuda_runtime.h>
#include <cuda_fp16.h>
#include <cstdint>

// ---------------------------------------------------------------------------
// Problem dims (fixed by reference setup_inputs)
// ---------------------------------------------------------------------------
constexpr int TOK = 8192;   // 4*2048 tokens
constexpr int DIM = 2048;
constexpr int HID = 8192;
constexpr int QBLK = 64;

// ---------------------------------------------------------------------------
// Device scratch (static globals -- no runtime allocation allowed)
// ---------------------------------------------------------------------------
static __device__ __half g_xh [(size_t)TOK * DIM];   //  32 MB
static __device__ __half g_wfc[(size_t)HID * DIM];   //  32 MB
static __device__ __half g_wpj[(size_t)DIM * HID];   //  32 MB
static __device__ __half g_h2 [(size_t)TOK * HID];   // 128 MB

__device__ __forceinline__ uint32_t smem_u32(const void* p) {
    return (uint32_t)__cvta_generic_to_shared(p);
}

// ---------------------------------------------------------------------------
// Kernel 1: blockwise int5 MSE quant-dequant. One THREAD per 64-elem block.
// base = max(amax,1e-8)/15; scan s = np.linspace(0.4,1.0,16) (f64, cast f32);
// q = round_half_even(v*inv) via magic-number trick; keep min-MSE scale.
// ---------------------------------------------------------------------------
__global__ void quant_kernel(const float4* __restrict__ w4,
                             __half* __restrict__ wq, int nblk) {
    int b = blockIdx.x * blockDim.x + threadIdx.x;
    if (b >= nblk) return;

    const float4* p = w4 + (size_t)b * (QBLK / 4);
    float v[QBLK];
    #pragma unroll
    for (int i = 0; i < QBLK / 4; i++) {
        float4 t = p[i];
        v[4*i] = t.x; v[4*i+1] = t.y; v[4*i+2] = t.z; v[4*i+3] = t.w;
    }
    float a = 0.f;
    #pragma unroll
    for (int i = 0; i < QBLK; i++) a = fmaxf(a, fabsf(v[i]));
    float base = __fdiv_rn(fmaxf(a, 1e-8f), 15.0f);

    const float MAGIC = 12582912.0f;   // 1.5 * 2^23 -> round half to even
    float best_err = INFINITY, best_scale = base, best_inv = 0.f;

    #pragma unroll 1
    for (int it = 0; it < 16; it++) {
        double sd = 0.4 + (double)it * (0.6 / 15.0);
        float s = (it == 15) ? 1.0f : (float)sd;
        float scale = base * s;
        float inv = __fdiv_rn(1.0f, scale);
        float e = 0.f;
        #pragma unroll
        for (int i = 0; i < QBLK; i++) {
            float q = fmaf(v[i], inv, MAGIC) - MAGIC;     // rne(v*inv)
            q = fminf(fmaxf(q, -15.f), 15.f);
            float d = fmaf(q, scale, -v[i]);
            e = fmaf(d, d, e);
        }
        if (e < best_err) { best_err = e; best_scale = scale; best_inv = inv; }
    }

    uint4 outv[QBLK / 8];
    __half2* hp = reinterpret_cast<__half2*>(outv);
    #pragma unroll
    for (int i = 0; i < QBLK / 2; i++) {
        float q0 = fmaf(v[2*i],   best_inv, MAGIC) - MAGIC;
        float q1 = fmaf(v[2*i+1], best_inv, MAGIC) - MAGIC;
        q0 = fminf(fmaxf(q0, -15.f), 15.f) * best_scale;
        q1 = fminf(fmaxf(q1, -15.f), 15.f) * best_scale;
        hp[i] = __floats2half2_rn(q0, q1);
    }
    uint4* dst = reinterpret_cast<uint4*>(wq + (size_t)b * QBLK);
    #pragma unroll
    for (int i = 0; i < QBLK / 8; i++) dst[i] = outv[i];
}

// ---------------------------------------------------------------------------
// Kernel 2: x fp32 -> fp16
// ---------------------------------------------------------------------------
__global__ void f2h_kernel(const float4* __restrict__ in, int n4) {
    int i = blockIdx.x * blockDim.x + threadIdx.x;
    if (i < n4) {
        float4 t = in[i];
        __half2* out = reinterpret_cast<__half2*>(g_xh);
        out[2*i]   = __floats2half2_rn(t.x, t.y);
        out[2*i+1] = __floats2half2_rn(t.z, t.w);
    }
}

// ---------------------------------------------------------------------------
// GEMM: C[M,N] = A[M,K] @ B[N,K]^T, fp16 in, fp32 acc.
// CTA tile 128x256xBK64, 8 warps (2x4), warp tile 64x64, m16n8k16 HMMA,
// 3-stage cp.async pipeline (fill kt+2 issued before compute on kt),
// padded smem rows (72 halves = 144B -> ldmatrix conflict-free).
// ---------------------------------------------------------------------------
constexpr int BM = 128, BN = 256, BK = 64, STAGES = 3;
constexpr int LDS = BK + 8;                         // 72 halves / row
constexpr int A_HALVES = BM * LDS;                  // per stage
constexpr int B_HALVES = BN * LDS;
constexpr int STAGE_HALVES = A_HALVES + B_HALVES;
constexpr int DSMEM_BYTES = STAGES * STAGE_HALVES * 2;   // 165,888 B

template <bool RELU_SQ>
__device__ __forceinline__ void gemm_body(const __half* __restrict__ A,
                                          const __half* __restrict__ B,
                                          __half* __restrict__ Ch,
                                          float* __restrict__ Cf,
                                          int N, int K) {
    extern __shared__ __align__(16) __half sm[];

    const int tid  = threadIdx.x;
    const int lane = tid & 31;
    const int warp = tid >> 5;
    const int wm   = warp >> 2;   // 0..1 : 64-row slab
    const int wn   = warp & 3;    // 0..3 : 64-col slab
    const int bm   = blockIdx.y * BM;
    const int bn   = blockIdx.x * BN;
    const int NKT  = K / BK;

    auto fill_stage = [&](int kt) {
        __half* As = sm + (kt % STAGES) * STAGE_HALVES;
        __half* Bs = As + A_HALVES;
        const int k0 = kt * BK;
        #pragma unroll
        for (int i = 0; i < 4; i++) {                 // A: 128 rows x 8 chunks
            int c = tid + i * 256, r = c >> 3, j = c & 7;
            const __half* src = A + (size_t)(bm + r) * K + k0 + j * 8;
            unsigned d = smem_u32(&As[r * LDS + j * 8]);
            asm volatile("cp.async.cg.shared.global [%0],[%1],16;"
                         :: "r"(d), "l"(src) : "memory");
        }
        #pragma unroll
        for (int i = 0; i < 8; i++) {                 // B: 256 rows x 8 chunks
            int c = tid + i * 256, r = c >> 3, j = c & 7;
            const __half* src = B + (size_t)(bn + r) * K + k0 + j * 8;
            unsigned d = smem_u32(&Bs[r * LDS + j * 8]);
            asm volatile("cp.async.cg.shared.global [%0],[%1],16;"
                         :: "r"(d), "l"(src) : "memory");
        }
    };

    float acc[4][8][4];
    #pragma unroll
    for (int i = 0; i < 4; i++)
        #pragma unroll
        for (int j = 0; j < 8; j++)
            #pragma unroll
            for (int k = 0; k < 4; k++) acc[i][j][k] = 0.f;

    // Prologue: stages 0,1
    fill_stage(0);
    asm volatile("cp.async.commit_group;" ::: "memory");
    fill_stage(1);
    asm volatile("cp.async.commit_group;" ::: "memory");

    for (int kt = 0; kt < NKT; kt++) {
        asm volatile("cp.async.wait_group 1;" ::: "memory");  // stage kt resident
        __syncthreads();

        if (kt + 2 < NKT) fill_stage(kt + 2);
        asm volatile("cp.async.commit_group;" ::: "memory");  // empty at tail: keeps count

        const __half* As = sm + (kt % STAGES) * STAGE_HALVES;
        const __half* Bs = As + A_HALVES;

        #pragma unroll
        for (int ks = 0; ks < 4; ks++) {              // 4 x K16 per stage
            uint32_t af[4][4];
            #pragma unroll
            for (int mi = 0; mi < 4; mi++) {
                int r = wm * 64 + mi * 16 + (lane & 15);
                int c = ks * 16 + (lane >> 4) * 8;
                unsigned addr = smem_u32(&As[r * LDS + c]);
                asm volatile(
                    "ldmatrix.sync.aligned.m8n8.x4.shared.b16 {%0,%1,%2,%3},[%4];"
                    : "=r"(af[mi][0]), "=r"(af[mi][1]),
                      "=r"(af[mi][2]), "=r"(af[mi][3])
                    : "r"(addr));
            }
            uint32_t bf[8][2];
            #pragma unroll
            for (int nb = 0; nb < 4; nb++) {
                int t    = lane >> 3;  // 0..3: (n-half, k-half) tiles
                int nrow = wn * 64 + nb * 16 + (t >> 1) * 8 + (lane & 7);
                int c    = ks * 16 + (t & 1) * 8;
                unsigned addr = smem_u32(&Bs[nrow * LDS + c]);
                uint32_t r0, r1, r2, r3;
                asm volatile(
                    "ldmatrix.sync.aligned.m8n8.x4.shared.b16 {%0,%1,%2,%3},[%4];"
                    : "=r"(r0), "=r"(r1), "=r"(r2), "=r"(r3) : "r"(addr));
                bf[nb * 2][0]     = r0; bf[nb * 2][1]     = r1;
                bf[nb * 2 + 1][0] = r2; bf[nb * 2 + 1][1] = r3;
            }
            #pragma unroll
            for (int mi = 0; mi < 4; mi++)
                #pragma unroll
                for (int ni = 0; ni < 8; ni++)
                    asm volatile(
                        "mma.sync.aligned.m16n8k16.row.col.f32.f16.f16.f32 "
                        "{%0,%1,%2,%3},{%4,%5,%6,%7},{%8,%9},{%0,%1,%2,%3};"
                        : "+f"(acc[mi][ni][0]), "+f"(acc[mi][ni][1]),
                          "+f"(acc[mi][ni][2]), "+f"(acc[mi][ni][3])
                        : "r"(af[mi][0]), "r"(af[mi][1]),
                          "r"(af[mi][2]), "r"(af[mi][3]),
                          "r"(bf[ni][0]), "r"(bf[ni][1]));
        }
        __syncthreads();
    }

    // Epilogue: c-frag (m16n8): c0,c1 at (lane/4, (lane%4)*2), c2,c3 at +8 rows
    const int row0 = bm + wm * 64 + (lane >> 2);
    const int col0 = bn + wn * 64 + (lane & 3) * 2;
    #pragma unroll
    for (int mi = 0; mi < 4; mi++)
        #pragma unroll
        for (int ni = 0; ni < 8; ni++) {
            int r = row0 + mi * 16;
            int c = col0 + ni * 8;
            if (RELU_SQ) {
                float x0 = fmaxf(acc[mi][ni][0], 0.f); x0 *= x0;
                float x1 = fmaxf(acc[mi][ni][1], 0.f); x1 *= x1;
                float y0 = fmaxf(acc[mi][ni][2], 0.f); y0 *= y0;
                float y1 = fmaxf(acc[mi][ni][3], 0.f); y1 *= y1;
                *reinterpret_cast<__half2*>(&Ch[(size_t)r * N + c]) =
                    __floats2half2_rn(x0, x1);
                *reinterpret_cast<__half2*>(&Ch[(size_t)(r + 8) * N + c]) =
                    __floats2half2_rn(y0, y1);
            } else {
                *reinterpret_cast<float2*>(&Cf[(size_t)r * N + c]) =
                    make_float2(acc[mi][ni][0], acc[mi][ni][1]);
                *reinterpret_cast<float2*>(&Cf[(size_t)(r + 8) * N + c]) =
                    make_float2(acc[mi][ni][2], acc[mi][ni][3]);
            }
        }
}

__global__ __launch_bounds__(256, 1) void gemm1_kernel() {
    gemm_body<true>(g_xh, g_wfc, g_h2, nullptr, HID, DIM);   // h2 = relu(x@wfc^T)^2
}
__global__ __launch_bounds__(256, 1) void gemm2_kernel(float* __restrict__ out) {
    gemm_body<false>(g_h2, g_wpj, nullptr, out, DIM, HID);   // out = h2 @ wpj^T
}

// ---------------------------------------------------------------------------
// Launch
// ---------------------------------------------------------------------------
extern "C" void kernel_launch(void* const* d_in, const int* in_sizes, int n_in,
                              void* d_out, int out_size) {
    const float* x   = (const float*)d_in[0];
    const float* wfc = (const float*)d_in[1];
    const float* wpj = (const float*)d_in[2];
    float* out = (float*)d_out;

    cudaFuncSetAttribute(gemm1_kernel, cudaFuncAttributeMaxDynamicSharedMemorySize, DSMEM_BYTES);
    cudaFuncSetAttribute(gemm2_kernel, cudaFuncAttributeMaxDynamicSharedMemorySize, DSMEM_BYTES);

    int n4 = TOK * DIM / 4;
    f2h_kernel<<<(n4 + 255) / 256, 256>>>((const float4*)x, n4);

    int nblk = HID * DIM / QBLK;    // 262144 per weight
    __half* d_wfc_q; cudaGetSymbolAddress((void**)&d_wfc_q, g_wfc);
    __half* d_wpj_q; cudaGetSymbolAddress((void**)&d_wpj_q, g_wpj);
    quant_kernel<<<(nblk + 255) / 256, 256>>>((const float4*)wfc, d_wfc_q, nblk);
    quant_kernel<<<(nblk + 255) / 256, 256>>>((const float4*)wpj, d_wpj_q, nblk);

    gemm1_kernel<<<dim3(HID / BN, TOK / BM), 256, DSMEM_BYTES>>>();
    gemm2_kernel<<<dim3(DIM / BN, TOK / BM), 256, DSMEM_BYTES>>>(out);

    (void)in_sizes; (void)n_in; (void)out_size;
}

// round 6
// speedup vs baseline: 1.2468x; 1.0027x over previous
#include <cuda_runtime.h>
#include <cuda_fp16.h>
#include <cstdint>

// ---------------------------------------------------------------------------
// Problem dims (fixed by reference setup_inputs)
// ---------------------------------------------------------------------------
constexpr int TOK = 8192;   // 4*2048 tokens
constexpr int DIM = 2048;
constexpr int HID = 8192;
constexpr int QBLK = 64;

// ---------------------------------------------------------------------------
// Device scratch (static globals -- no runtime allocation allowed)
// ---------------------------------------------------------------------------
static __device__ __half g_xh [(size_t)TOK * DIM];   //  32 MB
static __device__ __half g_wfc[(size_t)HID * DIM];   //  32 MB
static __device__ __half g_wpj[(size_t)DIM * HID];   //  32 MB
static __device__ __half g_h2 [(size_t)TOK * HID];   // 128 MB

__device__ __forceinline__ uint32_t smem_u32(const void* p) {
    return (uint32_t)__cvta_generic_to_shared(p);
}

// ---------------------------------------------------------------------------
// Kernel 1: blockwise int5 MSE quant-dequant. One THREAD per 64-elem block.
// ---------------------------------------------------------------------------
__global__ void quant_kernel(const float4* __restrict__ w4,
                             __half* __restrict__ wq, int nblk) {
    int b = blockIdx.x * blockDim.x + threadIdx.x;
    if (b >= nblk) return;

    const float4* p = w4 + (size_t)b * (QBLK / 4);
    float v[QBLK];
    #pragma unroll
    for (int i = 0; i < QBLK / 4; i++) {
        float4 t = p[i];
        v[4*i] = t.x; v[4*i+1] = t.y; v[4*i+2] = t.z; v[4*i+3] = t.w;
    }
    float a = 0.f;
    #pragma unroll
    for (int i = 0; i < QBLK; i++) a = fmaxf(a, fabsf(v[i]));
    float base = __fdiv_rn(fmaxf(a, 1e-8f), 15.0f);

    const float MAGIC = 12582912.0f;   // 1.5 * 2^23 -> round half to even
    float best_err = INFINITY, best_scale = base, best_inv = 0.f;

    #pragma unroll 1
    for (int it = 0; it < 16; it++) {
        double sd = 0.4 + (double)it * (0.6 / 15.0);
        float s = (it == 15) ? 1.0f : (float)sd;
        float scale = base * s;
        float inv = __fdiv_rn(1.0f, scale);
        float e = 0.f;
        #pragma unroll
        for (int i = 0; i < QBLK; i++) {
            float q = fmaf(v[i], inv, MAGIC) - MAGIC;     // rne(v*inv)
            q = fminf(fmaxf(q, -15.f), 15.f);
            float d = fmaf(q, scale, -v[i]);
            e = fmaf(d, d, e);
        }
        if (e < best_err) { best_err = e; best_scale = scale; best_inv = inv; }
    }

    uint4 outv[QBLK / 8];
    __half2* hp = reinterpret_cast<__half2*>(outv);
    #pragma unroll
    for (int i = 0; i < QBLK / 2; i++) {
        float q0 = fmaf(v[2*i],   best_inv, MAGIC) - MAGIC;
        float q1 = fmaf(v[2*i+1], best_inv, MAGIC) - MAGIC;
        q0 = fminf(fmaxf(q0, -15.f), 15.f) * best_scale;
        q1 = fminf(fmaxf(q1, -15.f), 15.f) * best_scale;
        hp[i] = __floats2half2_rn(q0, q1);
    }
    uint4* dst = reinterpret_cast<uint4*>(wq + (size_t)b * QBLK);
    #pragma unroll
    for (int i = 0; i < QBLK / 8; i++) dst[i] = outv[i];
}

// ---------------------------------------------------------------------------
// Kernel 2: x fp32 -> fp16
// ---------------------------------------------------------------------------
__global__ void f2h_kernel(const float4* __restrict__ in, int n4) {
    int i = blockIdx.x * blockDim.x + threadIdx.x;
    if (i < n4) {
        float4 t = in[i];
        __half2* out = reinterpret_cast<__half2*>(g_xh);
        out[2*i]   = __floats2half2_rn(t.x, t.y);
        out[2*i+1] = __floats2half2_rn(t.z, t.w);
    }
}

// ---------------------------------------------------------------------------
// GEMM: C[M,N] = A[M,K] @ B[N,K]^T, fp16 in, fp32 acc.
// CTA 128x256xBK64, 8 warps (2x4), warp tile 64x64, m16n8k16 HMMA,
// 3-stage cp.async pipeline, ONE syncthreads per k-stage, and explicit
// register fragment double-buffering across the 4 K16 sub-steps.
// ---------------------------------------------------------------------------
constexpr int BM = 128, BN = 256, BK = 64, STAGES = 3;
constexpr int LDS = BK + 8;                         // 72 halves / row
constexpr int A_HALVES = BM * LDS;
constexpr int B_HALVES = BN * LDS;
constexpr int STAGE_HALVES = A_HALVES + B_HALVES;
constexpr int DSMEM_BYTES = STAGES * STAGE_HALVES * 2;   // 165,888 B

template <bool RELU_SQ>
__device__ __forceinline__ void gemm_body(const __half* __restrict__ A,
                                          const __half* __restrict__ B,
                                          __half* __restrict__ Ch,
                                          float* __restrict__ Cf,
                                          int N, int K) {
    extern __shared__ __align__(16) __half sm[];

    const int tid  = threadIdx.x;
    const int lane = tid & 31;
    const int warp = tid >> 5;
    const int wm   = warp >> 2;   // 0..1 : 64-row slab
    const int wn   = warp & 3;    // 0..3 : 64-col slab
    const int bm   = blockIdx.y * BM;
    const int bn   = blockIdx.x * BN;
    const int NKT  = K / BK;

    auto fill_stage = [&](int kt) {
        __half* As = sm + (kt % STAGES) * STAGE_HALVES;
        __half* Bs = As + A_HALVES;
        const int k0 = kt * BK;
        #pragma unroll
        for (int i = 0; i < 4; i++) {                 // A: 128 rows x 8 chunks
            int c = tid + i * 256, r = c >> 3, j = c & 7;
            const __half* src = A + (size_t)(bm + r) * K + k0 + j * 8;
            unsigned d = smem_u32(&As[r * LDS + j * 8]);
            asm volatile("cp.async.cg.shared.global [%0],[%1],16;"
                         :: "r"(d), "l"(src) : "memory");
        }
        #pragma unroll
        for (int i = 0; i < 8; i++) {                 // B: 256 rows x 8 chunks
            int c = tid + i * 256, r = c >> 3, j = c & 7;
            const __half* src = B + (size_t)(bn + r) * K + k0 + j * 8;
            unsigned d = smem_u32(&Bs[r * LDS + j * 8]);
            asm volatile("cp.async.cg.shared.global [%0],[%1],16;"
                         :: "r"(d), "l"(src) : "memory");
        }
    };

    // Fragment loaders for one K16 sub-step
    auto load_a = [&](const __half* As, int ks, uint32_t af[4][4]) {
        #pragma unroll
        for (int mi = 0; mi < 4; mi++) {
            int r = wm * 64 + mi * 16 + (lane & 15);
            int c = ks * 16 + (lane >> 4) * 8;
            unsigned addr = smem_u32(&As[r * LDS + c]);
            asm volatile(
                "ldmatrix.sync.aligned.m8n8.x4.shared.b16 {%0,%1,%2,%3},[%4];"
                : "=r"(af[mi][0]), "=r"(af[mi][1]),
                  "=r"(af[mi][2]), "=r"(af[mi][3])
                : "r"(addr));
        }
    };
    auto load_b = [&](const __half* Bs, int ks, uint32_t bf[8][2]) {
        #pragma unroll
        for (int nb = 0; nb < 4; nb++) {
            int t    = lane >> 3;  // 0..3: (n-half, k-half) tiles
            int nrow = wn * 64 + nb * 16 + (t >> 1) * 8 + (lane & 7);
            int c    = ks * 16 + (t & 1) * 8;
            unsigned addr = smem_u32(&Bs[nrow * LDS + c]);
            uint32_t r0, r1, r2, r3;
            asm volatile(
                "ldmatrix.sync.aligned.m8n8.x4.shared.b16 {%0,%1,%2,%3},[%4];"
                : "=r"(r0), "=r"(r1), "=r"(r2), "=r"(r3) : "r"(addr));
            bf[nb * 2][0]     = r0; bf[nb * 2][1]     = r1;
            bf[nb * 2 + 1][0] = r2; bf[nb * 2 + 1][1] = r3;
        }
    };

    float acc[4][8][4];
    #pragma unroll
    for (int i = 0; i < 4; i++)
        #pragma unroll
        for (int j = 0; j < 8; j++)
            #pragma unroll
            for (int k = 0; k < 4; k++) acc[i][j][k] = 0.f;

    // Prologue: stages 0,1
    fill_stage(0);
    asm volatile("cp.async.commit_group;" ::: "memory");
    fill_stage(1);
    asm volatile("cp.async.commit_group;" ::: "memory");

    uint32_t af[2][4][4];
    uint32_t bf[2][8][2];

    for (int kt = 0; kt < NKT; kt++) {
        asm volatile("cp.async.wait_group 1;" ::: "memory");  // stage kt resident
        __syncthreads();   // also orders: compute(kt-1) done before fill(kt+2)

        if (kt + 2 < NKT) fill_stage(kt + 2);
        asm volatile("cp.async.commit_group;" ::: "memory");  // empty at tail: keeps count

        const __half* As = sm + (kt % STAGES) * STAGE_HALVES;
        const __half* Bs = As + A_HALVES;

        // prime sub-step 0
        load_a(As, 0, af[0]);
        load_b(Bs, 0, bf[0]);

        #pragma unroll
        for (int ks = 0; ks < 4; ks++) {
            const int cur = ks & 1, nxt = cur ^ 1;
            if (ks < 3) {               // prefetch ks+1 under the MMA shadow
                load_a(As, ks + 1, af[nxt]);
                load_b(Bs, ks + 1, bf[nxt]);
            }
            #pragma unroll
            for (int mi = 0; mi < 4; mi++)
                #pragma unroll
                for (int ni = 0; ni < 8; ni++)
                    asm volatile(
                        "mma.sync.aligned.m16n8k16.row.col.f32.f16.f16.f32 "
                        "{%0,%1,%2,%3},{%4,%5,%6,%7},{%8,%9},{%0,%1,%2,%3};"
                        : "+f"(acc[mi][ni][0]), "+f"(acc[mi][ni][1]),
                          "+f"(acc[mi][ni][2]), "+f"(acc[mi][ni][3])
                        : "r"(af[cur][mi][0]), "r"(af[cur][mi][1]),
                          "r"(af[cur][mi][2]), "r"(af[cur][mi][3]),
                          "r"(bf[cur][ni][0]), "r"(bf[cur][ni][1]));
        }
        // no end-of-loop barrier: next iteration's top barrier provides it
    }

    // Epilogue: c-frag (m16n8): c0,c1 at (lane/4, (lane%4)*2), c2,c3 at +8 rows
    const int row0 = bm + wm * 64 + (lane >> 2);
    const int col0 = bn + wn * 64 + (lane & 3) * 2;
    #pragma unroll
    for (int mi = 0; mi < 4; mi++)
        #pragma unroll
        for (int ni = 0; ni < 8; ni++) {
            int r = row0 + mi * 16;
            int c = col0 + ni * 8;
            if (RELU_SQ) {
                float x0 = fmaxf(acc[mi][ni][0], 0.f); x0 *= x0;
                float x1 = fmaxf(acc[mi][ni][1], 0.f); x1 *= x1;
                float y0 = fmaxf(acc[mi][ni][2], 0.f); y0 *= y0;
                float y1 = fmaxf(acc[mi][ni][3], 0.f); y1 *= y1;
                *reinterpret_cast<__half2*>(&Ch[(size_t)r * N + c]) =
                    __floats2half2_rn(x0, x1);
                *reinterpret_cast<__half2*>(&Ch[(size_t)(r + 8) * N + c]) =
                    __floats2half2_rn(y0, y1);
            } else {
                *reinterpret_cast<float2*>(&Cf[(size_t)r * N + c]) =
                    make_float2(acc[mi][ni][0], acc[mi][ni][1]);
                *reinterpret_cast<float2*>(&Cf[(size_t)(r + 8) * N + c]) =
                    make_float2(acc[mi][ni][2], acc[mi][ni][3]);
            }
        }
}

__global__ __launch_bounds__(256, 1) void gemm1_kernel() {
    gemm_body<true>(g_xh, g_wfc, g_h2, nullptr, HID, DIM);   // h2 = relu(x@wfc^T)^2
}
__global__ __launch_bounds__(256, 1) void gemm2_kernel(float* __restrict__ out) {
    gemm_body<false>(g_h2, g_wpj, nullptr, out, DIM, HID);   // out = h2 @ wpj^T
}

// ---------------------------------------------------------------------------
// Launch
// ---------------------------------------------------------------------------
extern "C" void kernel_launch(void* const* d_in, const int* in_sizes, int n_in,
                              void* d_out, int out_size) {
    const float* x   = (const float*)d_in[0];
    const float* wfc = (const float*)d_in[1];
    const float* wpj = (const float*)d_in[2];
    float* out = (float*)d_out;

    cudaFuncSetAttribute(gemm1_kernel, cudaFuncAttributeMaxDynamicSharedMemorySize, DSMEM_BYTES);
    cudaFuncSetAttribute(gemm2_kernel, cudaFuncAttributeMaxDynamicSharedMemorySize, DSMEM_BYTES);

    int n4 = TOK * DIM / 4;
    f2h_kernel<<<(n4 + 255) / 256, 256>>>((const float4*)x, n4);

    int nblk = HID * DIM / QBLK;    // 262144 per weight
    __half* d_wfc_q; cudaGetSymbolAddress((void**)&d_wfc_q, g_wfc);
    __half* d_wpj_q; cudaGetSymbolAddress((void**)&d_wpj_q, g_wpj);
    quant_kernel<<<(nblk + 255) / 256, 256>>>((const float4*)wfc, d_wfc_q, nblk);
    quant_kernel<<<(nblk + 255) / 256, 256>>>((const float4*)wpj, d_wpj_q, nblk);

    gemm1_kernel<<<dim3(HID / BN, TOK / BM), 256, DSMEM_BYTES>>>();
    gemm2_kernel<<<dim3(DIM / BN, TOK / BM), 256, DSMEM_BYTES>>>(out);

    (void)in_sizes; (void)n_in; (void)out_size;
}